// round 8
// baseline (speedup 1.0000x reference)
#include <cuda_runtime.h>

#define TPB 128
#define XPAD 62   // even stride: 8B-aligned float2 LDS/STS; at most 2-way bank conflicts

typedef unsigned long long ull;

// ---- packed fp32x2 helpers (FFMA2/FMUL2 via PTX f32x2) ----
__device__ __forceinline__ ull pk(float lo, float hi) {
    ull r; asm("mov.b64 %0, {%1, %2};" : "=l"(r) : "f"(lo), "f"(hi)); return r;
}
__device__ __forceinline__ float lo2(ull v) { return __uint_as_float((unsigned)v); }
__device__ __forceinline__ float hi2(ull v) { return __uint_as_float((unsigned)(v >> 32)); }
__device__ __forceinline__ ull fma2(ull a, ull b, ull c) {
    ull d; asm("fma.rn.f32x2 %0, %1, %2, %3;" : "=l"(d) : "l"(a), "l"(b), "l"(c)); return d;
}
__device__ __forceinline__ ull mul2(ull a, ull b) {
    ull d; asm("mul.rn.f32x2 %0, %1, %2;" : "=l"(d) : "l"(a), "l"(b)); return d;
}
__device__ __forceinline__ float ex2(float x) {
    float r; asm("ex2.approx.f32 %0, %1;" : "=f"(r) : "f"(x)); return r;
}

// One thread = one batch problem.
// Softmax row-constant terms (x_i.u + bq.bk) are dropped (invariant over keys).
// S'_ij = (x_i^T M x_j + r.x_j)*log2(e),  M = Wq^T Wk, r = Wk^T bq  (pre-scaled)
// out_i = sum_j 2^{S'_ij} vsum_j / sum_j 2^{S'_ij},  vsum_j = wv.x_j + cv
//
// smem constants (duplicated float2 pairs = ready fma2 operands):
// [0..35] M(a*6+d)*L2E, [36..41] r*L2E, [42..47] wv, [48] cv
//
// __launch_bounds__(128, 3): cap regs at 168 — the proven no-spill sweet spot
// for this live-state shape (R1 fit identical packed G[6][5]+hp/vp at 168).
__global__ __launch_bounds__(TPB, 3) void attn_kernel(
    const float* __restrict__ x,
    const float* __restrict__ Wk, const float* __restrict__ bk,
    const float* __restrict__ Wq, const float* __restrict__ bq,
    const float* __restrict__ Wv, const float* __restrict__ bv,
    float* __restrict__ out)
{
    __shared__ float2 cst[49];
    __shared__ float  xs[TPB * XPAD];
    const int t = threadIdx.x;

    // ---- per-block precompute of dup-packed constants (L2-cached W reads) ----
    if (t < 49) {
        const float L2E = 1.4426950408889634f;
        float s = 0.f;
        if (t < 36) {                    // M[a][b] = sum_e Wq[e][a] Wk[e][b]  (*L2E)
            int a = t / 6, b = t % 6;
            #pragma unroll
            for (int e = 0; e < 6; e++) s += Wq[e*6 + a] * Wk[e*6 + b];
            s *= L2E;
        } else if (t < 42) {             // r[b] = sum_e bq[e] Wk[e][b]  (*L2E)
            int b = t - 36;
            #pragma unroll
            for (int e = 0; e < 6; e++) s += bq[e] * Wk[e*6 + b];
            s *= L2E;
        } else if (t < 48) {             // wv[d] = colsum(Wv)
            int d = t - 42;
            #pragma unroll
            for (int e = 0; e < 6; e++) s += Wv[e*6 + d];
        } else {                         // cv = sum(bv)
            #pragma unroll
            for (int e = 0; e < 6; e++) s += bv[e];
        }
        cst[t] = make_float2(s, s);
    }

    // ---- coalesced staging: 128 problems * 60 floats = 1920 float4 per block ----
    const float4* xg = (const float4*)(x + (size_t)blockIdx.x * (TPB * 60));
    #pragma unroll
    for (int i = 0; i < 15; i++) {
        float4 v = xg[i * TPB + t];
        int g = (i * TPB + t) * 4;       // 60 % 4 == 0 -> float4 never crosses a problem
        int b = g / 60, e = g % 60;
        float2* dst = (float2*)&xs[b * XPAD + e];   // (b*62+e) even -> 8B aligned
        dst[0] = make_float2(v.x, v.y);
        dst[1] = make_float2(v.z, v.w);
    }
    __syncthreads();

    const float2* x2 = (const float2*)&xs[t * XPAD];   // per-problem view, 8B aligned
    const ull*    C  = reinterpret_cast<const ull*>(cst);

    // ---- phase 1: packed over key pairs. G_j = M x_j, h_j = r.x_j, vsum_j ----
    ull G[6][5], hp[5], vp[5];
    #pragma unroll
    for (int jp = 0; jp < 5; jp++) {
        float2 a0 = x2[jp*6 + 0], a1 = x2[jp*6 + 1], a2 = x2[jp*6 + 2];  // key 2jp
        float2 b0 = x2[jp*6 + 3], b1 = x2[jp*6 + 4], b2 = x2[jp*6 + 5];  // key 2jp+1
        ull xx[6];
        xx[0] = pk(a0.x, b0.x); xx[1] = pk(a0.y, b0.y);
        xx[2] = pk(a1.x, b1.x); xx[3] = pk(a1.y, b1.y);
        xx[4] = pk(a2.x, b2.x); xx[5] = pk(a2.y, b2.y);

        #pragma unroll
        for (int a = 0; a < 6; a++) {
            ull g = mul2(C[a*6 + 0], xx[0]);
            #pragma unroll
            for (int d = 1; d < 6; d++) g = fma2(C[a*6 + d], xx[d], g);
            G[a][jp] = g;
        }
        ull h = mul2(C[36], xx[0]);
        ull v = fma2(C[42], xx[0], C[48]);
        #pragma unroll
        for (int d = 1; d < 6; d++) {
            h = fma2(C[36 + d], xx[d], h);
            v = fma2(C[42 + d], xx[d], v);
        }
        hp[jp] = h;
        vp[jp] = v;
    }

    // ---- phase 2: per query, 2 scores at a time; scalar softmax tail ----
    float res[10];
    #pragma unroll
    for (int i = 0; i < 10; i++) {
        float2 q0 = x2[i*3 + 0], q1 = x2[i*3 + 1], q2 = x2[i*3 + 2];
        ull X[6];
        X[0] = pk(q0.x, q0.x); X[1] = pk(q0.y, q0.y);
        X[2] = pk(q1.x, q1.x); X[3] = pk(q1.y, q1.y);
        X[4] = pk(q2.x, q2.x); X[5] = pk(q2.y, q2.y);

        float num = 0.f, den = 0.f;
        #pragma unroll
        for (int jp = 0; jp < 5; jp++) {
            ull s = fma2(X[0], G[0][jp], hp[jp]);
            #pragma unroll
            for (int a = 1; a < 6; a++) s = fma2(X[a], G[a][jp], s);
            float ea = ex2(lo2(s));
            float eb = ex2(hi2(s));
            num = __fmaf_rn(ea, lo2(vp[jp]), num);
            num = __fmaf_rn(eb, hi2(vp[jp]), num);
            den += ea + eb;
        }
        res[i] = __fdividef(num, den);
    }

    // ---- output: 5 x float2 per thread ----
    float2* op = (float2*)(out + (size_t)(blockIdx.x * TPB + t) * 10);
    #pragma unroll
    for (int p = 0; p < 5; p++) op[p] = make_float2(res[2*p], res[2*p + 1]);
}

extern "C" void kernel_launch(void* const* d_in, const int* in_sizes, int n_in,
                              void* d_out, int out_size) {
    const float* x  = (const float*)d_in[0];
    const float* Wk = (const float*)d_in[1];
    const float* bk = (const float*)d_in[2];
    const float* Wq = (const float*)d_in[3];
    const float* bq = (const float*)d_in[4];
    const float* Wv = (const float*)d_in[5];
    const float* bv = (const float*)d_in[6];
    int B = in_sizes[0] / 60;            // 524288
    int blocks = B / TPB;                // 4096
    attn_kernel<<<blocks, TPB>>>(x, Wk, bk, Wq, bq, Wv, bv, (float*)d_out);
}

// round 9
// speedup vs baseline: 1.4637x; 1.4637x over previous
#include <cuda_runtime.h>

#define TPB 128
#define XPAD 62   // per-problem smem stride in floats (even: 8B-aligned float2; 62%32=30 -> only 2-way bank conflicts)

typedef unsigned long long ull;

// ---- packed fp32x2 helpers (FFMA2 via PTX fma.rn.f32x2) ----
__device__ __forceinline__ ull pk(float lo, float hi) {
    ull r; asm("mov.b64 %0, {%1, %2};" : "=l"(r) : "f"(lo), "f"(hi)); return r;
}
__device__ __forceinline__ float lo2(ull v) { return __uint_as_float((unsigned)v); }
__device__ __forceinline__ float hi2(ull v) { return __uint_as_float((unsigned)(v >> 32)); }
__device__ __forceinline__ ull fma2(ull a, ull b, ull c) {
    ull d; asm("fma.rn.f32x2 %0, %1, %2, %3;" : "=l"(d) : "l"(a), "l"(b), "l"(c)); return d;
}
__device__ __forceinline__ float ex2(float x) {
    float r; asm("ex2.approx.f32 %0, %1;" : "=f"(r) : "f"(x)); return r;
}

// One thread = one batch problem.  (R1 structure, surgical cuts only.)
// Constants pre-scaled by log2(e) so softmax uses raw ex2 (no hidden FMUL).
// S'_ij = x_i^T M x_j + x_i.u + r.x_j + c   (all *L2E; row-constant terms kept --
//         identical DAG shape to R1), out_i = sum 2^s v / sum 2^s.
__global__ __launch_bounds__(TPB) void attn_kernel(
    const float* __restrict__ x,
    const float* __restrict__ Wk, const float* __restrict__ bk,
    const float* __restrict__ Wq, const float* __restrict__ bq,
    const float* __restrict__ Wv, const float* __restrict__ bv,
    float* __restrict__ out)
{
    __shared__ float cst[64];            // M[36], u[6], r[6], c, wv[6], cv  (score terms *L2E)
    __shared__ float xs[TPB * XPAD];     // staged x, stride-62 padded
    const int t = threadIdx.x;

    // ---- per-block precompute of batch-independent constants (L2-cached W reads) ----
    if (t < 56) {
        const float L2E = 1.4426950408889634f;
        float s = 0.f;
        if (t < 36) {                    // M[a][b] = sum_e Wq[e][a] * Wk[e][b]  (*L2E)
            int a = t / 6, b = t % 6;
            #pragma unroll
            for (int e = 0; e < 6; e++) s += Wq[e*6 + a] * Wk[e*6 + b];
            cst[t] = s * L2E;
        } else if (t < 42) {             // u[a] = sum_e Wq[e][a] * bk[e]  (*L2E)
            int a = t - 36;
            #pragma unroll
            for (int e = 0; e < 6; e++) s += Wq[e*6 + a] * bk[e];
            cst[t] = s * L2E;
        } else if (t < 48) {             // r[b] = sum_e bq[e] * Wk[e][b]  (*L2E)
            int b = t - 42;
            #pragma unroll
            for (int e = 0; e < 6; e++) s += bq[e] * Wk[e*6 + b];
            cst[t] = s * L2E;
        } else if (t == 48) {            // c = bq.bk  (*L2E)
            #pragma unroll
            for (int e = 0; e < 6; e++) s += bq[e] * bk[e];
            cst[48] = s * L2E;
        } else if (t < 55) {             // wv[d] = colsum(Wv)
            int d = t - 49;
            #pragma unroll
            for (int e = 0; e < 6; e++) s += Wv[e*6 + d];
            cst[t] = s;
        } else {                         // cv = sum(bv)
            #pragma unroll
            for (int e = 0; e < 6; e++) s += bv[e];
            cst[55] = s;
        }
    }

    // ---- coalesced staging: 128 problems * 60 floats = 1920 float4 per block ----
    const float4* xg = (const float4*)(x + (size_t)blockIdx.x * (TPB * 60));
    #pragma unroll
    for (int i = 0; i < 15; i++) {
        float4 v = xg[i * TPB + t];
        int g = (i * TPB + t) * 4;       // 60 % 4 == 0 -> a float4 never crosses a problem boundary
        int b = g / 60, e = g % 60;
        float2* dst = (float2*)&xs[b * XPAD + e];   // (b*62+e) even -> 8B aligned
        dst[0] = make_float2(v.x, v.y);
        dst[1] = make_float2(v.z, v.w);
    }
    __syncthreads();

    // ---- load constants into registers (exactly as R1) ----
    float M[36], uu[6], rr[6], wv[6];
    #pragma unroll
    for (int i = 0; i < 36; i++) M[i] = cst[i];
    #pragma unroll
    for (int i = 0; i < 6; i++) { uu[i] = cst[36 + i]; rr[i] = cst[42 + i]; wv[i] = cst[49 + i]; }
    const float c0 = cst[48], cv = cst[55];

    const float* xp = &xs[t * XPAD];

    // ---- phase 1 (R1 structure): scalar compute per key pair, pack at the end ----
    ull G2[6][5];      // G packed over key pairs: (G_j[a], G_{j+1}[a])
    ull hp[5], vp[5];  // (h_j, h_{j+1}), (vsum_j, vsum_{j+1})
    #pragma unroll
    for (int jp = 0; jp < 5; jp++) {
        float g0[6], g1[6];
        #pragma unroll
        for (int a = 0; a < 6; a++) { g0[a] = uu[a]; g1[a] = uu[a]; }
        float h0 = c0, h1 = c0, s0 = cv, s1 = cv;
        #pragma unroll
        for (int d = 0; d < 6; d++) {
            float x0 = xp[jp*12 + d];
            float x1 = xp[jp*12 + 6 + d];
            h0 += rr[d] * x0;  h1 += rr[d] * x1;
            s0 += wv[d] * x0;  s1 += wv[d] * x1;
            #pragma unroll
            for (int a = 0; a < 6; a++) {
                g0[a] += M[a*6 + d] * x0;
                g1[a] += M[a*6 + d] * x1;
            }
        }
        #pragma unroll
        for (int a = 0; a < 6; a++) G2[a][jp] = pk(g0[a], g1[a]);
        hp[jp] = pk(h0, h1);
        vp[jp] = pk(s0, s1);
    }

    // ---- phase 2 (R1 structure): 2 scores at a time via FFMA2; raw ex2 ----
    float res[10];
    #pragma unroll
    for (int i = 0; i < 10; i++) {
        ull X[6];
        #pragma unroll
        for (int a = 0; a < 6; a++) { float xv = xp[i*6 + a]; X[a] = pk(xv, xv); }
        float num = 0.f, den = 0.f;
        #pragma unroll
        for (int jp = 0; jp < 5; jp++) {
            ull s = hp[jp];
            #pragma unroll
            for (int a = 0; a < 6; a++) s = fma2(X[a], G2[a][jp], s);
            float ea = ex2(lo2(s));      // was __expf -> FMUL+MUFU; now pure MUFU
            float eb = ex2(hi2(s));
            den += ea + eb;
            num = __fmaf_rn(ea, lo2(vp[jp]), num);
            num = __fmaf_rn(eb, hi2(vp[jp]), num);
        }
        res[i] = __fdividef(num, den);
    }

    // ---- output: 5 x float2 per thread (40B base offset -> 8B aligned) ----
    float2* op = (float2*)(out + (size_t)(blockIdx.x * TPB + t) * 10);
    #pragma unroll
    for (int p = 0; p < 5; p++) op[p] = make_float2(res[2*p], res[2*p + 1]);
}

extern "C" void kernel_launch(void* const* d_in, const int* in_sizes, int n_in,
                              void* d_out, int out_size) {
    const float* x  = (const float*)d_in[0];
    const float* Wk = (const float*)d_in[1];
    const float* bk = (const float*)d_in[2];
    const float* Wq = (const float*)d_in[3];
    const float* bq = (const float*)d_in[4];
    const float* Wv = (const float*)d_in[5];
    const float* bv = (const float*)d_in[6];
    int B = in_sizes[0] / 60;            // 524288
    int blocks = B / TPB;                // 4096
    attn_kernel<<<blocks, TPB>>>(x, Wk, bk, Wq, bq, Wv, bv, (float*)d_out);
}

// round 10
// speedup vs baseline: 1.5743x; 1.0756x over previous
#include <cuda_runtime.h>

#define TPB 128
#define XPAD 62   // per-problem smem stride (even -> 8B-aligned LDS.64; 2-way conflicts max)

typedef unsigned long long ull;

// ---- packed fp32x2 helpers (FFMA2/FMUL2 via PTX f32x2) ----
__device__ __forceinline__ ull pk(float lo, float hi) {
    ull r; asm("mov.b64 %0, {%1, %2};" : "=l"(r) : "f"(lo), "f"(hi)); return r;
}
__device__ __forceinline__ float lo2(ull v) { return __uint_as_float((unsigned)v); }
__device__ __forceinline__ float hi2(ull v) { return __uint_as_float((unsigned)(v >> 32)); }
__device__ __forceinline__ ull fma2(ull a, ull b, ull c) {
    ull d; asm("fma.rn.f32x2 %0, %1, %2, %3;" : "=l"(d) : "l"(a), "l"(b), "l"(c)); return d;
}
__device__ __forceinline__ ull mul2(ull a, ull b) {
    ull d; asm("mul.rn.f32x2 %0, %1, %2;" : "=l"(d) : "l"(a), "l"(b)); return d;
}
__device__ __forceinline__ float ex2(float x) {
    float r; asm("ex2.approx.f32 %0, %1;" : "=f"(r) : "f"(x)); return r;
}

// One thread = one batch problem.  TRANSPOSED smem layout: x[j][d] at d*10+j, so the
// key-pair packed operand (x_{2jp}[d], x_{2jp+1}[d]) is ONE aligned LDS.64 (no pk MOVs).
// Softmax row-constant terms (x_i.u + bq.bk) dropped (invariant over keys).
// S'_ij = (x_i^T M x_j + r.x_j)*log2(e),  out_i = sum 2^s vsum / sum 2^s, vsum_j = wv.x_j + cv.
//
// smem constants (dup-packed float2 = ready fma2 operands):
// [0..35] M(a*6+d)*L2E, [36..41] r*L2E, [42..47] wv, [48] cv
__global__ __launch_bounds__(TPB, 3) void attn_kernel(
    const float* __restrict__ x,
    const float* __restrict__ Wk, const float* __restrict__ bk,
    const float* __restrict__ Wq, const float* __restrict__ bq,
    const float* __restrict__ Wv, const float* __restrict__ bv,
    float* __restrict__ out)
{
    __shared__ float2 cst[49];
    __shared__ float  xs[TPB * XPAD];
    const int t = threadIdx.x;

    // ---- per-block precompute of dup-packed constants (L2-cached W reads) ----
    if (t < 49) {
        const float L2E = 1.4426950408889634f;
        float s = 0.f;
        if (t < 36) {                    // M[a][b] = sum_e Wq[e][a] Wk[e][b]  (*L2E)
            int a = t / 6, b = t % 6;
            #pragma unroll
            for (int e = 0; e < 6; e++) s += Wq[e*6 + a] * Wk[e*6 + b];
            s *= L2E;
        } else if (t < 42) {             // r[b] = sum_e bq[e] Wk[e][b]  (*L2E)
            int b = t - 36;
            #pragma unroll
            for (int e = 0; e < 6; e++) s += bq[e] * Wk[e*6 + b];
            s *= L2E;
        } else if (t < 48) {             // wv[d] = colsum(Wv)
            int d = t - 42;
            #pragma unroll
            for (int e = 0; e < 6; e++) s += Wv[e*6 + d];
        } else {                         // cv = sum(bv)
            #pragma unroll
            for (int e = 0; e < 6; e++) s += bv[e];
        }
        cst[t] = make_float2(s, s);
    }

    // ---- coalesced staging with TRANSPOSE: element (b, j, d) -> xs[b*62 + d*10 + j] ----
    // float4 at base e (e = 4k): d0 = e%6 in {0,2,4}; elements 0,1 never roll over a key;
    // elements 2,3 roll into key j0+1 only when d0 == 4 (addr - 59).
    const float4* xg = (const float4*)(x + (size_t)blockIdx.x * (TPB * 60));
    #pragma unroll
    for (int i = 0; i < 15; i++) {
        float4 v = xg[i * TPB + t];
        int g  = (i * TPB + t) * 4;
        int b  = g / 60;
        int e  = g - b * 60;
        int j0 = e / 6;
        int d0 = e - 6 * j0;
        int a0 = b * XPAD + d0 * 10 + j0;
        int ro = (d0 == 4) ? 59 : 0;     // rollover reroute for elements 2,3
        xs[a0]           = v.x;
        xs[a0 + 10]      = v.y;
        xs[a0 + 20 - ro] = v.z;
        xs[a0 + 30 - ro] = v.w;
    }
    __syncthreads();

    const float* xp = &xs[t * XPAD];
    const ull*   XX = (const ull*)xp;               // packed key-pair view: XX[d*5 + jp]
    const ull*   C  = reinterpret_cast<const ull*>(cst);

    // ---- phase 1, d-outer, fully packed: G[a][jp] = (M x)_pair, hp = r.x, vp = wv.x + cv ----
    ull G[6][5], hp[5], vp[5];
    {   // d = 0
        ull xx0 = XX[0], xx1 = XX[1], xx2 = XX[2], xx3 = XX[3], xx4 = XX[4];
        #pragma unroll
        for (int a = 0; a < 6; a++) {
            ull m = C[a*6];
            G[a][0] = mul2(m, xx0); G[a][1] = mul2(m, xx1); G[a][2] = mul2(m, xx2);
            G[a][3] = mul2(m, xx3); G[a][4] = mul2(m, xx4);
        }
        ull r = C[36], w = C[42], cv = C[48];
        hp[0] = mul2(r, xx0); hp[1] = mul2(r, xx1); hp[2] = mul2(r, xx2);
        hp[3] = mul2(r, xx3); hp[4] = mul2(r, xx4);
        vp[0] = fma2(w, xx0, cv); vp[1] = fma2(w, xx1, cv); vp[2] = fma2(w, xx2, cv);
        vp[3] = fma2(w, xx3, cv); vp[4] = fma2(w, xx4, cv);
    }
    #pragma unroll
    for (int d = 1; d < 6; d++) {
        ull xx[5];
        #pragma unroll
        for (int jp = 0; jp < 5; jp++) xx[jp] = XX[d*5 + jp];   // direct LDS.64, no marshalling
        #pragma unroll
        for (int a = 0; a < 6; a++) {
            ull m = C[a*6 + d];
            #pragma unroll
            for (int jp = 0; jp < 5; jp++) G[a][jp] = fma2(m, xx[jp], G[a][jp]);
        }
        ull r = C[36 + d], w = C[42 + d];
        #pragma unroll
        for (int jp = 0; jp < 5; jp++) {
            hp[jp] = fma2(r, xx[jp], hp[jp]);
            vp[jp] = fma2(w, xx[jp], vp[jp]);
        }
    }

    // ---- phase 2 (R9 structure): per query, 2 scores via FFMA2; scalar tail; raw ex2 ----
    float res[10];
    #pragma unroll
    for (int i = 0; i < 10; i++) {
        ull X[6];
        #pragma unroll
        for (int a = 0; a < 6; a++) { float xv = xp[a*10 + i]; X[a] = pk(xv, xv); }
        float num = 0.f, den = 0.f;
        #pragma unroll
        for (int jp = 0; jp < 5; jp++) {
            ull s = fma2(X[0], G[0][jp], hp[jp]);
            #pragma unroll
            for (int a = 1; a < 6; a++) s = fma2(X[a], G[a][jp], s);
            float ea = ex2(lo2(s));
            float eb = ex2(hi2(s));
            den += ea + eb;
            num = __fmaf_rn(ea, lo2(vp[jp]), num);
            num = __fmaf_rn(eb, hi2(vp[jp]), num);
        }
        res[i] = __fdividef(num, den);
    }

    // ---- output: 5 x float2 per thread ----
    float2* op = (float2*)(out + (size_t)(blockIdx.x * TPB + t) * 10);
    #pragma unroll
    for (int p = 0; p < 5; p++) op[p] = make_float2(res[2*p], res[2*p + 1]);
}

extern "C" void kernel_launch(void* const* d_in, const int* in_sizes, int n_in,
                              void* d_out, int out_size) {
    const float* x  = (const float*)d_in[0];
    const float* Wk = (const float*)d_in[1];
    const float* bk = (const float*)d_in[2];
    const float* Wq = (const float*)d_in[3];
    const float* bq = (const float*)d_in[4];
    const float* Wv = (const float*)d_in[5];
    const float* bv = (const float*)d_in[6];
    int B = in_sizes[0] / 60;            // 524288
    int blocks = B / TPB;                // 4096
    attn_kernel<<<blocks, TPB>>>(x, Wk, bk, Wq, bq, Wv, bv, (float*)d_out);
}